// round 10
// baseline (speedup 1.0000x reference)
#include <cuda_runtime.h>
#include <math.h>

// Problem constants (fixed shapes)
#define B  64
#define E  512
#define N  8192
#define M  64
#define AD 70          // M + 6
#define EPS 1e-8f

// ---------------- device scratch (no allocation allowed) ----------------
__device__ float g_k[B * M];
__device__ float g_knorm[B];
__device__ float g_beta[B];
__device__ float g_g[B];
__device__ float g_s[B * 3];
__device__ float g_y[B];
__device__ float g_S[B];        // softmax denominator
__device__ float g_Spow[B];     // sharpening denominator
__device__ float g_e[B * N];    // exp(beta*sim)

__device__ __forceinline__ float softplus_f(float x) {
    return (x > 20.f) ? x : log1pf(expf(x));
}

// ---------------- K1: addressing vector + activations + zeroing ----------------
__global__ void k1_addr(const float* __restrict__ emb,
                        const float* __restrict__ W,
                        const float* __restrict__ bias,
                        float* __restrict__ out_md) {
    int b   = blockIdx.x;
    int tid = threadIdx.x;
    int c   = tid >> 7;        // 0..3 chunk of E
    int t   = tid & 127;       // output slot

    __shared__ float part[4][AD];
    __shared__ float s_addr[AD];

    if (t < AD) {
        float acc = 0.f;
        const float* er = emb + (size_t)b * E + c * 128;
        const float* Wp = W + (size_t)(c * 128) * AD + t;
        #pragma unroll 8
        for (int e = 0; e < 128; e++)
            acc = fmaf(er[e], Wp[(size_t)e * AD], acc);
        part[c][t] = acc;
    }
    if (tid < M)      out_md[b * M + tid] = 0.f;
    if (tid == M)     g_S[b]    = 0.f;
    if (tid == M + 1) g_Spow[b] = 0.f;
    __syncthreads();

    if (tid < AD) {
        float v = part[0][tid] + part[1][tid] + part[2][tid] + part[3][tid] + bias[tid];
        s_addr[tid] = v;
        if (tid < M) g_k[b * M + tid] = v;
    }
    __syncthreads();

    if (tid < 32) {
        float a0 = s_addr[tid], a1 = s_addr[tid + 32];
        float sq = a0 * a0 + a1 * a1;
        #pragma unroll
        for (int off = 16; off; off >>= 1)
            sq += __shfl_xor_sync(0xffffffffu, sq, off);
        if (tid == 0) {
            g_knorm[b] = sqrtf(sq);
            g_beta[b]  = softplus_f(s_addr[M]);
            g_g[b]     = 1.f / (1.f + __expf(-s_addr[M + 1]));
            float a = s_addr[M + 2], cc = s_addr[M + 3], d = s_addr[M + 4];
            float mx = fmaxf(a, fmaxf(cc, d));
            float ea = __expf(a - mx), eb = __expf(cc - mx), ec = __expf(d - mx);
            float inv = 1.f / (ea + eb + ec);
            g_s[b * 3 + 0] = ea * inv;
            g_s[b * 3 + 1] = eb * inv;
            g_s[b * 3 + 2] = ec * inv;
            g_y[b] = 1.f + softplus_f(s_addr[M + 5]);
        }
    }
}

// ---------------- K2: content addressing (pass 1 over memory, 128 MB) ----------------
__global__ void k2_sim(const float* __restrict__ mem) {
    int b     = blockIdx.y;
    int chunk = blockIdx.x;
    int warp  = threadIdx.x >> 5;
    int lane  = threadIdx.x & 31;
    int grp   = lane >> 3;     // 0..3 : which row of the 4-row batch
    int lg    = lane & 7;      // 0..7 : position within row

    __shared__ float sk[M];
    __shared__ float swsum[8];
    if (threadIdx.x < M) sk[threadIdx.x] = g_k[b * M + threadIdx.x];
    __syncthreads();

    float beta = g_beta[b];
    float kn   = g_knorm[b];
    float4 ka = *(const float4*)&sk[lg * 8];
    float4 kb = *(const float4*)&sk[lg * 8 + 4];

    const float4* memp = (const float4*)(mem + (size_t)b * N * M);
    int n0 = chunk * 512 + warp * 64;

    float wsum = 0.f;
    #pragma unroll 4
    for (int i = 0; i < 64; i += 8) {
        int r0 = n0 + i + grp;
        int r1 = r0 + 4;
        float4 va0 = memp[(size_t)r0 * 16 + lg * 2];
        float4 vb0 = memp[(size_t)r0 * 16 + lg * 2 + 1];
        float4 va1 = memp[(size_t)r1 * 16 + lg * 2];
        float4 vb1 = memp[(size_t)r1 * 16 + lg * 2 + 1];

        #pragma unroll
        for (int u = 0; u < 2; u++) {
            float4 va = u ? va1 : va0;
            float4 vb = u ? vb1 : vb0;
            int r = u ? r1 : r0;
            float dot = va.x * ka.x + va.y * ka.y + va.z * ka.z + va.w * ka.w
                      + vb.x * kb.x + vb.y * kb.y + vb.z * kb.z + vb.w * kb.w;
            float nsq = va.x * va.x + va.y * va.y + va.z * va.z + va.w * va.w
                      + vb.x * vb.x + vb.y * vb.y + vb.z * vb.z + vb.w * vb.w;
            #pragma unroll
            for (int off = 4; off; off >>= 1) {
                dot += __shfl_xor_sync(0xffffffffu, dot, off);
                nsq += __shfl_xor_sync(0xffffffffu, nsq, off);
            }
            float sim = dot / (sqrtf(nsq) * kn + EPS);
            float ev  = __expf(beta * sim);   // no max-sub needed: |beta*sim| small
            if (lg == 0) g_e[b * N + r] = ev;
            wsum += ev;                       // counted 8x per row
        }
    }
    wsum *= 0.125f;
    #pragma unroll
    for (int off = 16; off; off >>= 1)
        wsum += __shfl_xor_sync(0xffffffffu, wsum, off);
    if (lane == 0) swsum[warp] = wsum;
    __syncthreads();
    if (threadIdx.x == 0) {
        float s = 0.f;
        #pragma unroll
        for (int i = 0; i < 8; i++) s += swsum[i];
        atomicAdd(&g_S[b], s);
    }
}

// ---------------- K3: Spow-only reduction (L2-hot, 4 MB, no stores) ----------------
// Computes sum_n (w_s[n]^y) per batch so k34 can write final normalized outputs.
__global__ void k3_spow(const float* __restrict__ w_prev) {
    int idx = blockIdx.x * blockDim.x + threadIdx.x;   // over B*N, 512-thread blocks
    int b = idx >> 13;
    int n = idx & (N - 1);

    float S    = g_S[b];
    float gg   = g_g[b];
    float invS = gg / S;
    float om   = 1.f - gg;
    float s0 = g_s[b * 3 + 0], s1 = g_s[b * 3 + 1], s2 = g_s[b * 3 + 2];

    const float* eb  = g_e    + (size_t)b * N;
    const float* wpb = w_prev + (size_t)b * N;
    int nm = (n + N - 1) & (N - 1);
    int np = (n + 1) & (N - 1);

    float wg_m = fmaf(invS, eb[nm], om * wpb[nm]);
    float wg_0 = fmaf(invS, eb[n],  om * wpb[n]);
    float wg_p = fmaf(invS, eb[np], om * wpb[np]);
    float ws   = s0 * wg_m + s1 * wg_0 + s2 * wg_p;
    float v    = __powf(ws, g_y[b]);     // ws > 0 strictly

    #pragma unroll
    for (int off = 16; off; off >>= 1)
        v += __shfl_xor_sync(0xffffffffu, v, off);
    __shared__ float sred[16];
    int warp = threadIdx.x >> 5, lane = threadIdx.x & 31;
    if (lane == 0) sred[warp] = v;
    __syncthreads();
    if (threadIdx.x == 0) {
        float s = 0.f;
        #pragma unroll
        for (int i = 0; i < 16; i++) s += sred[i];
        atomicAdd(&g_Spow[b], s);
    }
}

// ---------------- K34: fused shift + sharpen + normalized read (pass 2, 128 MB) ----------------
// Spow is known, so wv = wpow * invP is FINAL: store normalized w, accumulate
// normalized md directly. Recomputing powf here is free (hidden under DRAM).
__global__ void k34_read(const float* __restrict__ mem,
                         const float* __restrict__ w_prev,
                         float* __restrict__ out_md,
                         float* __restrict__ out_w) {
    int b     = (B - 1) - blockIdx.y;  // reversed batch traversal
    int chunk = 15 - blockIdx.x;       // reversed chunk traversal
    int warp  = threadIdx.x >> 5;
    int lane  = threadIdx.x & 31;
    int grp   = lane >> 3;
    int lg    = lane & 7;
    int l7    = lane & 7;

    float S    = g_S[b];
    float gg   = g_g[b];
    float invS = gg / S;
    float om   = 1.f - gg;
    float s0 = g_s[b * 3 + 0], s1 = g_s[b * 3 + 1], s2 = g_s[b * 3 + 2];
    float y  = g_y[b];
    float invP = 1.f / (g_Spow[b] + EPS);

    const float4* memp = (const float4*)(mem + (size_t)b * N * M);
    const float*  eb   = g_e    + (size_t)b * N;
    const float*  wpb  = w_prev + (size_t)b * N;
    int n0 = chunk * 512 + warp * 64;

    float acc[8] = {0.f, 0.f, 0.f, 0.f, 0.f, 0.f, 0.f, 0.f};

    #pragma unroll 2
    for (int i = 0; i < 64; i += 8) {
        int r0 = n0 + i + grp;
        int r1 = r0 + 4;
        float4 va0 = memp[(size_t)r0 * 16 + lg * 2];
        float4 vb0 = memp[(size_t)r0 * 16 + lg * 2 + 1];
        float4 va1 = memp[(size_t)r1 * 16 + lg * 2];
        float4 vb1 = memp[(size_t)r1 * 16 + lg * 2 + 1];

        // shift + sharpen for row rr = n0+i+(lane&7); lanes 8..31 duplicate 0..7
        int rr = n0 + i + l7;
        int nm = (rr + N - 1) & (N - 1);
        int np = (rr + 1) & (N - 1);
        float wg_m = fmaf(invS, eb[nm], om * wpb[nm]);
        float wg_0 = fmaf(invS, eb[rr], om * wpb[rr]);
        float wg_p = fmaf(invS, eb[np], om * wpb[np]);
        float ws   = s0 * wg_m + s1 * wg_0 + s2 * wg_p;
        float wv   = __powf(ws, y) * invP;   // FINAL normalized weight

        if (lane < 8)
            out_w[(size_t)b * N + rr] = wv;

        float wv0 = __shfl_sync(0xffffffffu, wv, grp);
        float wv1 = __shfl_sync(0xffffffffu, wv, 4 + grp);

        acc[0] = fmaf(va0.x, wv0, acc[0]);
        acc[1] = fmaf(va0.y, wv0, acc[1]);
        acc[2] = fmaf(va0.z, wv0, acc[2]);
        acc[3] = fmaf(va0.w, wv0, acc[3]);
        acc[4] = fmaf(vb0.x, wv0, acc[4]);
        acc[5] = fmaf(vb0.y, wv0, acc[5]);
        acc[6] = fmaf(vb0.z, wv0, acc[6]);
        acc[7] = fmaf(vb0.w, wv0, acc[7]);
        acc[0] = fmaf(va1.x, wv1, acc[0]);
        acc[1] = fmaf(va1.y, wv1, acc[1]);
        acc[2] = fmaf(va1.z, wv1, acc[2]);
        acc[3] = fmaf(va1.w, wv1, acc[3]);
        acc[4] = fmaf(vb1.x, wv1, acc[4]);
        acc[5] = fmaf(vb1.y, wv1, acc[5]);
        acc[6] = fmaf(vb1.z, wv1, acc[6]);
        acc[7] = fmaf(vb1.w, wv1, acc[7]);
    }

    // reduce acc across the 4 groups (lanes lg, lg+8, lg+16, lg+24)
    #pragma unroll
    for (int j = 0; j < 8; j++) {
        acc[j] += __shfl_xor_sync(0xffffffffu, acc[j], 8);
        acc[j] += __shfl_xor_sync(0xffffffffu, acc[j], 16);
    }

    __shared__ float sacc[8][M];
    if (grp == 0) {
        #pragma unroll
        for (int j = 0; j < 8; j++)
            sacc[warp][lg * 8 + j] = acc[j];
    }
    __syncthreads();
    if (threadIdx.x < M) {
        float s = 0.f;
        #pragma unroll
        for (int w = 0; w < 8; w++) s += sacc[w][threadIdx.x];
        atomicAdd(&out_md[b * M + threadIdx.x], s);
    }
}

// ---------------- launch ----------------
extern "C" void kernel_launch(void* const* d_in, const int* in_sizes, int n_in,
                              void* d_out, int out_size) {
    const float* emb  = (const float*)d_in[0];   // [B,E]
    const float* wp   = (const float*)d_in[1];   // [B,N]
    const float* mem  = (const float*)d_in[2];   // [B,N,M]
    const float* W    = (const float*)d_in[3];   // [E,M+6]
    const float* bias = (const float*)d_in[4];   // [M+6]

    float* out    = (float*)d_out;
    float* out_md = out;                 // [B,M]  first output
    float* out_w  = out + (size_t)B * M; // [B,N]  second output

    k1_addr <<<B, 512>>>(emb, W, bias, out_md);
    k2_sim  <<<dim3(16, B), 256>>>(mem);
    k3_spow <<<(B * N) / 512, 512>>>(wp);
    k34_read<<<dim3(16, B), 256>>>(mem, wp, out_md, out_w);
}

// round 12
// speedup vs baseline: 1.0246x; 1.0246x over previous
#include <cuda_runtime.h>
#include <math.h>

// Problem constants (fixed shapes)
#define B  64
#define E  512
#define N  8192
#define M  64
#define AD 70          // M + 6
#define EPS 1e-8f

#define PGRID 592      // 148 SMs x 4 CTAs: single fully-resident wave
#define ITEMS 2048     // B * 32 chunks of 256 rows

// ---------------- device scratch (no allocation allowed) ----------------
__device__ float g_k[B * M];
__device__ float g_knorm[B];
__device__ float g_beta[B];
__device__ float g_g[B];
__device__ float g_s[B * 3];
__device__ float g_y[B];
__device__ float g_S[B];          // softmax denominator
__device__ float g_Spow[B];       // sharpening denominator
__device__ float g_md[B * M];     // unnormalized read result
__device__ float g_e[B * N];      // exp(beta*sim)
__device__ unsigned g_done;       // k34 grid-sync counter

__device__ __forceinline__ float softplus_f(float x) {
    return (x > 20.f) ? x : log1pf(expf(x));
}

// ---------------- K1: addressing vector + activations + zeroing ----------------
__global__ void k1_addr(const float* __restrict__ emb,
                        const float* __restrict__ W,
                        const float* __restrict__ bias) {
    int b   = blockIdx.x;
    int tid = threadIdx.x;
    int c   = tid >> 7;        // 0..3 chunk of E
    int t   = tid & 127;       // output slot

    __shared__ float part[4][AD];
    __shared__ float s_addr[AD];

    if (t < AD) {
        float acc = 0.f;
        const float* er = emb + (size_t)b * E + c * 128;
        const float* Wp = W + (size_t)(c * 128) * AD + t;
        #pragma unroll 8
        for (int e = 0; e < 128; e++)
            acc = fmaf(er[e], Wp[(size_t)e * AD], acc);
        part[c][t] = acc;
    }
    if (tid < M)      g_md[b * M + tid] = 0.f;
    if (tid == M)     g_S[b]    = 0.f;
    if (tid == M + 1) g_Spow[b] = 0.f;
    if (b == 0 && tid == M + 2) g_done = 0u;
    __syncthreads();

    if (tid < AD) {
        float v = part[0][tid] + part[1][tid] + part[2][tid] + part[3][tid] + bias[tid];
        s_addr[tid] = v;
        if (tid < M) g_k[b * M + tid] = v;
    }
    __syncthreads();

    if (tid < 32) {
        float a0 = s_addr[tid], a1 = s_addr[tid + 32];
        float sq = a0 * a0 + a1 * a1;
        #pragma unroll
        for (int off = 16; off; off >>= 1)
            sq += __shfl_xor_sync(0xffffffffu, sq, off);
        if (tid == 0) {
            g_knorm[b] = sqrtf(sq);
            g_beta[b]  = softplus_f(s_addr[M]);
            g_g[b]     = 1.f / (1.f + __expf(-s_addr[M + 1]));
            float a = s_addr[M + 2], cc = s_addr[M + 3], d = s_addr[M + 4];
            float mx = fmaxf(a, fmaxf(cc, d));
            float ea = __expf(a - mx), eb = __expf(cc - mx), ec = __expf(d - mx);
            float inv = 1.f / (ea + eb + ec);
            g_s[b * 3 + 0] = ea * inv;
            g_s[b * 3 + 1] = eb * inv;
            g_s[b * 3 + 2] = ec * inv;
            g_y[b] = 1.f + softplus_f(s_addr[M + 5]);
        }
    }
}

// ---------------- K2: content addressing (pass 1, 128 MB), persistent ----------------
// 592 resident CTAs grid-stride over 2048 items (b, 256-row chunk).
__global__ void __launch_bounds__(256, 4) k2_sim(const float* __restrict__ mem) {
    int warp = threadIdx.x >> 5;
    int lane = threadIdx.x & 31;
    int grp  = lane >> 3;      // 0..3 : row within the 4-row batch
    int lg   = lane & 7;       // 0..7 : position within row

    __shared__ float sk[M];
    __shared__ float swsum[8];

    for (int it = blockIdx.x; it < ITEMS; it += PGRID) {
        int b     = it >> 5;
        int chunk = it & 31;

        __syncthreads();   // protect sk from previous item's readers
        if (threadIdx.x < M) sk[threadIdx.x] = g_k[b * M + threadIdx.x];
        __syncthreads();

        float beta = g_beta[b];
        float kn   = g_knorm[b];
        float4 ka = *(const float4*)&sk[lg * 8];
        float4 kb = *(const float4*)&sk[lg * 8 + 4];

        const float4* memp = (const float4*)(mem + (size_t)b * N * M);
        int n0 = chunk * 256 + warp * 32;

        float wsum = 0.f;
        #pragma unroll 2
        for (int i = 0; i < 32; i += 8) {
            int r0 = n0 + i + grp;
            int r1 = r0 + 4;
            float4 va0 = memp[(size_t)r0 * 16 + lg * 2];
            float4 vb0 = memp[(size_t)r0 * 16 + lg * 2 + 1];
            float4 va1 = memp[(size_t)r1 * 16 + lg * 2];
            float4 vb1 = memp[(size_t)r1 * 16 + lg * 2 + 1];

            #pragma unroll
            for (int u = 0; u < 2; u++) {
                float4 va = u ? va1 : va0;
                float4 vb = u ? vb1 : vb0;
                int r = u ? r1 : r0;
                float dot = va.x * ka.x + va.y * ka.y + va.z * ka.z + va.w * ka.w
                          + vb.x * kb.x + vb.y * kb.y + vb.z * kb.z + vb.w * kb.w;
                float nsq = va.x * va.x + va.y * va.y + va.z * va.z + va.w * va.w
                          + vb.x * vb.x + vb.y * vb.y + vb.z * vb.z + vb.w * vb.w;
                #pragma unroll
                for (int off = 4; off; off >>= 1) {
                    dot += __shfl_xor_sync(0xffffffffu, dot, off);
                    nsq += __shfl_xor_sync(0xffffffffu, nsq, off);
                }
                float sim = dot / (sqrtf(nsq) * kn + EPS);
                float ev  = __expf(beta * sim);   // |beta*sim| small: no max-sub
                if (lg == 0) g_e[b * N + r] = ev;
                wsum += ev;                       // counted 8x per row
            }
        }
        wsum *= 0.125f;
        #pragma unroll
        for (int off = 16; off; off >>= 1)
            wsum += __shfl_xor_sync(0xffffffffu, wsum, off);
        if (lane == 0) swsum[warp] = wsum;
        __syncthreads();
        if (threadIdx.x == 0) {
            float s = 0.f;
            #pragma unroll
            for (int i = 0; i < 8; i++) s += swsum[i];
            atomicAdd(&g_S[b], s);
        }
    }
}

// ---------------- K34: fused shift+sharpen+read + in-kernel sync + normalize ----------------
// Phase 1: 128 MB pass, accumulate unnormalized md and Spow, write unnormalized w.
// Grid-sync (all 592 CTAs resident by __launch_bounds__(256,4)): arrive + spin.
// Phase 2: rescale own w rows by 1/Spow; first B blocks emit normalized md.
__global__ void __launch_bounds__(256, 4) k34_read(const float* __restrict__ mem,
                                                   const float* __restrict__ w_prev,
                                                   float* __restrict__ out_md,
                                                   float* __restrict__ out_w) {
    int warp = threadIdx.x >> 5;
    int lane = threadIdx.x & 31;
    int grp  = lane >> 3;
    int lg   = lane & 7;

    __shared__ float sacc[8][M];
    __shared__ float sspow[8];

    // ---- phase 1: reversed traversal (L2 reuse of k2's tail) ----
    for (int base = blockIdx.x; base < ITEMS; base += PGRID) {
        int it    = (ITEMS - 1) - base;
        int b     = it >> 5;
        int chunk = it & 31;

        float S    = g_S[b];
        float gg   = g_g[b];
        float invS = gg / S;
        float om   = 1.f - gg;
        float s0 = g_s[b * 3 + 0], s1 = g_s[b * 3 + 1], s2 = g_s[b * 3 + 2];
        float y  = g_y[b];

        const float4* memp = (const float4*)(mem + (size_t)b * N * M);
        const float*  eb   = g_e    + (size_t)b * N;
        const float*  wpb  = w_prev + (size_t)b * N;
        int n0 = chunk * 256 + warp * 32;

        float acc[8] = {0.f, 0.f, 0.f, 0.f, 0.f, 0.f, 0.f, 0.f};
        float spow = 0.f;

        #pragma unroll 2
        for (int i = 0; i < 32; i += 8) {
            int r0 = n0 + i + grp;
            int r1 = r0 + 4;
            float4 va0 = memp[(size_t)r0 * 16 + lg * 2];
            float4 vb0 = memp[(size_t)r0 * 16 + lg * 2 + 1];
            float4 va1 = memp[(size_t)r1 * 16 + lg * 2];
            float4 vb1 = memp[(size_t)r1 * 16 + lg * 2 + 1];

            // shift+sharpen for row rr = n0+i+(lane&7); lanes 8..31 duplicate 0..7
            int rr = n0 + i + lg;
            int nm = (rr + N - 1) & (N - 1);
            int np = (rr + 1) & (N - 1);
            float wg_m = fmaf(invS, eb[nm], om * wpb[nm]);
            float wg_0 = fmaf(invS, eb[rr], om * wpb[rr]);
            float wg_p = fmaf(invS, eb[np], om * wpb[np]);
            float ws   = s0 * wg_m + s1 * wg_0 + s2 * wg_p;
            float wv   = __powf(ws, y);          // ws > 0 strictly

            if (lane < 8) {
                out_w[(size_t)b * N + rr] = wv;  // unnormalized; phase 2 scales
                spow += wv;
            }
            float wv0 = __shfl_sync(0xffffffffu, wv, grp);
            float wv1 = __shfl_sync(0xffffffffu, wv, 4 + grp);

            acc[0] = fmaf(va0.x, wv0, acc[0]);
            acc[1] = fmaf(va0.y, wv0, acc[1]);
            acc[2] = fmaf(va0.z, wv0, acc[2]);
            acc[3] = fmaf(va0.w, wv0, acc[3]);
            acc[4] = fmaf(vb0.x, wv0, acc[4]);
            acc[5] = fmaf(vb0.y, wv0, acc[5]);
            acc[6] = fmaf(vb0.z, wv0, acc[6]);
            acc[7] = fmaf(vb0.w, wv0, acc[7]);
            acc[0] = fmaf(va1.x, wv1, acc[0]);
            acc[1] = fmaf(va1.y, wv1, acc[1]);
            acc[2] = fmaf(va1.z, wv1, acc[2]);
            acc[3] = fmaf(va1.w, wv1, acc[3]);
            acc[4] = fmaf(vb1.x, wv1, acc[4]);
            acc[5] = fmaf(vb1.y, wv1, acc[5]);
            acc[6] = fmaf(vb1.z, wv1, acc[6]);
            acc[7] = fmaf(vb1.w, wv1, acc[7]);
        }

        // reduce acc across the 4 groups
        #pragma unroll
        for (int j = 0; j < 8; j++) {
            acc[j] += __shfl_xor_sync(0xffffffffu, acc[j], 8);
            acc[j] += __shfl_xor_sync(0xffffffffu, acc[j], 16);
        }
        #pragma unroll
        for (int off = 16; off; off >>= 1)
            spow += __shfl_xor_sync(0xffffffffu, spow, off);

        __syncthreads();   // protect shared from previous item
        if (grp == 0) {
            #pragma unroll
            for (int j = 0; j < 8; j++)
                sacc[warp][lg * 8 + j] = acc[j];
        }
        if (lane == 0) sspow[warp] = spow;
        __syncthreads();
        if (threadIdx.x < M) {
            float s = 0.f;
            #pragma unroll
            for (int w = 0; w < 8; w++) s += sacc[w][threadIdx.x];
            atomicAdd(&g_md[b * M + threadIdx.x], s);
        }
        if (threadIdx.x == M) {
            float s = 0.f;
            #pragma unroll
            for (int w = 0; w < 8; w++) s += sspow[w];
            atomicAdd(&g_Spow[b], s);
        }
    }

    // ---- grid sync: all PGRID CTAs are resident (592 = 148 x 4) ----
    if (threadIdx.x == 0) {
        __threadfence();
        atomicAdd(&g_done, 1u);
        while (atomicAdd(&g_done, 0u) < (unsigned)gridDim.x) { }
    }
    __syncthreads();

    // ---- phase 2: normalize own w rows; first B blocks emit md ----
    for (int base = blockIdx.x; base < ITEMS; base += PGRID) {
        int it    = (ITEMS - 1) - base;
        int b     = it >> 5;
        int chunk = it & 31;
        float invP = 1.f / (__ldcg(&g_Spow[b]) + EPS);
        size_t idx = (size_t)b * N + chunk * 256 + threadIdx.x;
        out_w[idx] *= invP;
    }
    if (blockIdx.x < B && threadIdx.x < M) {
        int b = blockIdx.x;
        float invP = 1.f / (__ldcg(&g_Spow[b]) + EPS);
        out_md[b * M + threadIdx.x] = __ldcg(&g_md[b * M + threadIdx.x]) * invP;
    }
}

// ---------------- launch ----------------
extern "C" void kernel_launch(void* const* d_in, const int* in_sizes, int n_in,
                              void* d_out, int out_size) {
    const float* emb  = (const float*)d_in[0];   // [B,E]
    const float* wp   = (const float*)d_in[1];   // [B,N]
    const float* mem  = (const float*)d_in[2];   // [B,N,M]
    const float* W    = (const float*)d_in[3];   // [E,M+6]
    const float* bias = (const float*)d_in[4];   // [M+6]

    float* out    = (float*)d_out;
    float* out_md = out;                 // [B,M]  first output
    float* out_w  = out + (size_t)B * M; // [B,N]  second output

    k1_addr <<<B, 512>>>(emb, W, bias);
    k2_sim  <<<PGRID, 256>>>(mem);
    k34_read<<<PGRID, 256>>>(mem, wp, out_md, out_w);
}